// round 1
// baseline (speedup 1.0000x reference)
#include <cuda_runtime.h>
#include <math.h>

// Problem constants (fixed shapes from reference setup_inputs)
#define BATCH   2
#define CH      256
#define FH      200
#define FW      304
#define FHW     (FH*FW)          // 60800 (divisible by 32)
#define NBOX    512
#define POOLED  7
#define NBINS   (POOLED*POOLED)  // 49
#define SCALE   0.25f

// SMEM staging stride (padded so bin rows are float4-aligned and reads are
// near conflict-free): 49 * 260 * 4B = 50960 B (dynamic smem)
#define SM_STRIDE 260
#define SM_BYTES  (NBINS * SM_STRIDE * 4)

// Scratch: NHWC copy of the feature map (124.6 MB). Static __device__ global
// is the sanctioned no-alloc scratch mechanism.
__device__ float g_nhwc[(size_t)BATCH * FHW * CH];

// ---------------------------------------------------------------------------
// Pass 1: NCHW -> NHWC transpose (per batch: [C, HW] -> [HW, C])
// Classic 32x32 tiled transpose; both sides fully coalesced.
// ---------------------------------------------------------------------------
__global__ void nchw_to_nhwc_kernel(const float* __restrict__ in) {
    __shared__ float tile[32][33];
    const int b  = blockIdx.z;
    const int p0 = blockIdx.x * 32;   // HW tile origin (HW % 32 == 0)
    const int c0 = blockIdx.y * 32;   // C tile origin  (C  % 32 == 0)
    const int tx = threadIdx.x, ty = threadIdx.y;

    const float* src = in     + (size_t)b * CH  * FHW;
    float*       dst = g_nhwc + (size_t)b * FHW * CH;

#pragma unroll
    for (int i = 0; i < 32; i += 8)
        tile[ty + i][tx] = src[(size_t)(c0 + ty + i) * FHW + (p0 + tx)];
    __syncthreads();
#pragma unroll
    for (int i = 0; i < 32; i += 8)
        dst[(size_t)(p0 + ty + i) * CH + (c0 + tx)] = tile[tx][ty + i];
}

// ---------------------------------------------------------------------------
// Pass 2: RoI Align gather. One CTA per box.
//   tid & 63  -> c4   (4 channels via float4; 64*4 = 256 channels)
//   tid >> 6  -> bin subset (bins g, g+4, g+8, ...) — each subset owns whole
//               bins, so the 2x2 sample max needs no cross-thread reduction.
// Sample geometry precomputed once per box into SMEM; invalid samples have
// their interpolation weights zeroed (bilinear -> exactly 0, matching the
// reference's where(valid, val, 0) before the max).
// Results staged in SMEM so the final per-box store (c*49+bin order) is
// fully coalesced.
// ---------------------------------------------------------------------------
__global__ void roi_align_kernel(const float* __restrict__ boxes,
                                 const int*   __restrict__ batch_idx,
                                 float*       __restrict__ out) {
    extern __shared__ float sm[];       // [NBINS][SM_STRIDE]
    __shared__ int   s_i0[28];          // 0..13: x axis, 14..27: y axis
    __shared__ int   s_i1[28];
    __shared__ float s_lo[28];          // "l" weight (toward +1 neighbor)
    __shared__ float s_hi[28];          // "h" weight (toward base neighbor)

    const int n   = blockIdx.x;
    const int tid = threadIdx.x;

    if (tid < 28) {
        const bool isY  = tid >= 14;
        const int  i    = isY ? tid - 14 : tid;
        const float start = boxes[n * 4 + (isY ? 1 : 0)] * SCALE;
        const float end   = boxes[n * 4 + (isY ? 3 : 2)] * SCALE;
        const float sz    = fmaxf(end - start, 1.0f);
        const float bin   = sz / (float)POOLED;
        const int   p     = i >> 1;
        const int   s     = i & 1;
        const float coord = start + ((float)p + ((float)s + 0.5f) * 0.5f) * bin;
        const int   limit = isY ? FH : FW;
        const bool  valid = (coord > -1.0f) && (coord < (float)limit);
        const float cc    = fminf(fmaxf(coord, 0.0f), (float)(limit - 1));
        const int   c0    = (int)floorf(cc);
        const int   c1    = min(c0 + 1, limit - 1);
        float l = cc - (float)c0;
        float h = 1.0f - l;
        if (!valid) { l = 0.0f; h = 0.0f; }
        s_i0[tid] = c0; s_i1[tid] = c1; s_lo[tid] = l; s_hi[tid] = h;
    }
    __syncthreads();

    const int c4 = tid & 63;
    const int g  = tid >> 6;
    const float4* __restrict__ F =
        (const float4*)g_nhwc + (size_t)batch_idx[n] * FHW * (CH / 4);

    for (int bin = g; bin < NBINS; bin += 4) {
        const int ph = bin / POOLED;
        const int pw = bin - ph * POOLED;
        float4 vmax = make_float4(-INFINITY, -INFINITY, -INFINITY, -INFINITY);

#pragma unroll
        for (int s = 0; s < 4; s++) {
            const int sy = s >> 1, sx = s & 1;
            const int iy = 14 + ph * 2 + sy;
            const int ix = pw * 2 + sx;
            const int y0 = s_i0[iy], y1 = s_i1[iy];
            const int x0 = s_i0[ix], x1 = s_i1[ix];
            const float hy = s_hi[iy], ly = s_lo[iy];
            const float hx = s_hi[ix], lx = s_lo[ix];

            const float4 f00 = F[(size_t)(y0 * FW + x0) * 64 + c4];
            const float4 f01 = F[(size_t)(y0 * FW + x1) * 64 + c4];
            const float4 f10 = F[(size_t)(y1 * FW + x0) * 64 + c4];
            const float4 f11 = F[(size_t)(y1 * FW + x1) * 64 + c4];

            const float w00 = hy * hx, w01 = hy * lx;
            const float w10 = ly * hx, w11 = ly * lx;

            float4 v;
            v.x = w00 * f00.x + w01 * f01.x + w10 * f10.x + w11 * f11.x;
            v.y = w00 * f00.y + w01 * f01.y + w10 * f10.y + w11 * f11.y;
            v.z = w00 * f00.z + w01 * f01.z + w10 * f10.z + w11 * f11.z;
            v.w = w00 * f00.w + w01 * f01.w + w10 * f10.w + w11 * f11.w;

            vmax.x = fmaxf(vmax.x, v.x);
            vmax.y = fmaxf(vmax.y, v.y);
            vmax.z = fmaxf(vmax.z, v.z);
            vmax.w = fmaxf(vmax.w, v.w);
        }
        // SM_STRIDE = 260 keeps bin rows 16B-aligned for float4 STS.
        *(float4*)(sm + bin * SM_STRIDE + 4 * c4) = vmax;
    }
    __syncthreads();

    // Coalesced store: out[n][c][ph][pw], 12544 contiguous floats per box.
    float* obase = out + (size_t)n * (CH * NBINS);
#pragma unroll 4
    for (int k = tid; k < CH * NBINS; k += 256) {
        const int c  = k / NBINS;
        const int bn = k - c * NBINS;
        obase[k] = sm[bn * SM_STRIDE + c];
    }
}

// ---------------------------------------------------------------------------
extern "C" void kernel_launch(void* const* d_in, const int* in_sizes, int n_in,
                              void* d_out, int out_size) {
    const float* feature   = (const float*)d_in[0];
    const float* boxes     = (const float*)d_in[1];
    const int*   batch_idx = (const int*)d_in[2];
    float*       out       = (float*)d_out;

    // Dynamic smem > 48KB needs the opt-in attribute (idempotent, host-side,
    // not a stream op — safe under graph capture).
    cudaFuncSetAttribute(roi_align_kernel,
                         cudaFuncAttributeMaxDynamicSharedMemorySize, SM_BYTES);

    dim3 tgrid(FHW / 32, CH / 32, BATCH);
    dim3 tblock(32, 8);
    nchw_to_nhwc_kernel<<<tgrid, tblock>>>(feature);

    roi_align_kernel<<<NBOX, 256, SM_BYTES>>>(boxes, batch_idx, out);
}

// round 2
// speedup vs baseline: 1.0547x; 1.0547x over previous
#include <cuda_runtime.h>
#include <math.h>

// Problem constants (fixed shapes from reference setup_inputs)
#define BATCH   2
#define CH      256
#define FH      200
#define FW      304
#define FHW     (FH*FW)          // 60800 (divisible by 128)
#define NBOX    512
#define POOLED  7
#define NBINS   (POOLED*POOLED)  // 49
#define SCALE   0.25f

// Gather staging: 49 bins x 132 floats (128 channels + pad) = 25872 B
#define SM_STRIDE 132
#define SM_BYTES  (NBINS * SM_STRIDE * 4)

// Scratch: NHWC copy of the feature map (124.6 MB).
__device__ float g_nhwc[(size_t)BATCH * FHW * CH];

// ---------------------------------------------------------------------------
// Pass 1: NCHW -> NHWC transpose, float4 loads along HW.
// Tile: 32 channels x 128 HW positions per CTA. Block (32,8).
//  - load: 4 x LDG.128 per thread (high MLP), scatter scalars into smem
//  - store: conflict-free LDS + fully coalesced 128B STG along C
// ---------------------------------------------------------------------------
__global__ void nchw_to_nhwc_kernel(const float4* __restrict__ in) {
    __shared__ float tile[128][33];
    const int b   = blockIdx.z;
    const int p04 = blockIdx.x * 32;   // float4 origin along HW (tile = 128 floats)
    const int c0  = blockIdx.y * 32;   // channel tile origin
    const int tx  = threadIdx.x, ty = threadIdx.y;

    const float4* src = in + (size_t)b * CH * (FHW / 4);
    float*        dst = g_nhwc + (size_t)b * FHW * CH;

#pragma unroll
    for (int i = 0; i < 4; i++) {
        const int cl = 8 * i + ty;
        const float4 v = src[(size_t)(c0 + cl) * (FHW / 4) + p04 + tx];
        tile[4 * tx + 0][cl] = v.x;
        tile[4 * tx + 1][cl] = v.y;
        tile[4 * tx + 2][cl] = v.z;
        tile[4 * tx + 3][cl] = v.w;
    }
    __syncthreads();

    const int p0 = p04 * 4;
#pragma unroll
    for (int i = 0; i < 16; i++) {
        const int hw = 8 * i + ty;
        dst[(size_t)(p0 + hw) * CH + c0 + tx] = tile[hw][tx];
    }
}

// ---------------------------------------------------------------------------
// Pass 2: RoI Align gather. TWO CTAs per box (blockIdx.y = channel half) so
// the grid is 1024 CTAs -> ~7 CTAs/SM -> ~80% occupancy (was 39% at 512).
//   tid & 31  -> c4 (4 channels via float4; 32*4 = 128 channels per CTA)
//   tid >> 5  -> bin subset (bins g, g+8, ...) — whole bins per subset, so
//                the 2x2 sample max needs no cross-thread reduction.
// Invalid samples have interpolation weights zeroed (== reference's
// where(valid, val, 0) before the max). Results staged in smem so the final
// per-box-half store (contiguous 6272 floats) is fully coalesced.
// ---------------------------------------------------------------------------
__global__ void roi_align_kernel(const float* __restrict__ boxes,
                                 const int*   __restrict__ batch_idx,
                                 float*       __restrict__ out) {
    __shared__ float sm[NBINS * SM_STRIDE];
    __shared__ int   s_i0[28];          // 0..13: x axis, 14..27: y axis
    __shared__ int   s_i1[28];
    __shared__ float s_lo[28];          // weight toward +1 neighbor
    __shared__ float s_hi[28];          // weight toward base neighbor

    const int n    = blockIdx.x;
    const int half = blockIdx.y;
    const int tid  = threadIdx.x;

    if (tid < 28) {
        const bool isY  = tid >= 14;
        const int  i    = isY ? tid - 14 : tid;
        const float start = boxes[n * 4 + (isY ? 1 : 0)] * SCALE;
        const float end   = boxes[n * 4 + (isY ? 3 : 2)] * SCALE;
        const float sz    = fmaxf(end - start, 1.0f);
        const float bin   = sz / (float)POOLED;
        const int   p     = i >> 1;
        const int   s     = i & 1;
        const float coord = start + ((float)p + ((float)s + 0.5f) * 0.5f) * bin;
        const int   limit = isY ? FH : FW;
        const bool  valid = (coord > -1.0f) && (coord < (float)limit);
        const float cc    = fminf(fmaxf(coord, 0.0f), (float)(limit - 1));
        const int   c0    = (int)floorf(cc);
        const int   c1    = min(c0 + 1, limit - 1);
        float l = cc - (float)c0;
        float h = 1.0f - l;
        if (!valid) { l = 0.0f; h = 0.0f; }
        s_i0[tid] = c0; s_i1[tid] = c1; s_lo[tid] = l; s_hi[tid] = h;
    }
    __syncthreads();

    const int c4 = tid & 31;            // float4 lane within this 128-ch half
    const int g  = tid >> 5;            // bin subset 0..7
    const float4* __restrict__ F =
        (const float4*)g_nhwc + (size_t)batch_idx[n] * FHW * (CH / 4)
                              + half * 32 + c4;

    for (int bin = g; bin < NBINS; bin += 8) {
        const int ph = bin / POOLED;
        const int pw = bin - ph * POOLED;
        float4 vmax = make_float4(-INFINITY, -INFINITY, -INFINITY, -INFINITY);

#pragma unroll
        for (int s = 0; s < 4; s++) {
            const int sy = s >> 1, sx = s & 1;
            const int iy = 14 + ph * 2 + sy;
            const int ix = pw * 2 + sx;
            const int y0 = s_i0[iy], y1 = s_i1[iy];
            const int x0 = s_i0[ix], x1 = s_i1[ix];
            const float hy = s_hi[iy], ly = s_lo[iy];
            const float hx = s_hi[ix], lx = s_lo[ix];

            const float4 f00 = F[(size_t)(y0 * FW + x0) * 64];
            const float4 f01 = F[(size_t)(y0 * FW + x1) * 64];
            const float4 f10 = F[(size_t)(y1 * FW + x0) * 64];
            const float4 f11 = F[(size_t)(y1 * FW + x1) * 64];

            const float w00 = hy * hx, w01 = hy * lx;
            const float w10 = ly * hx, w11 = ly * lx;

            float4 v;
            v.x = w00 * f00.x + w01 * f01.x + w10 * f10.x + w11 * f11.x;
            v.y = w00 * f00.y + w01 * f01.y + w10 * f10.y + w11 * f11.y;
            v.z = w00 * f00.z + w01 * f01.z + w10 * f10.z + w11 * f11.z;
            v.w = w00 * f00.w + w01 * f01.w + w10 * f10.w + w11 * f11.w;

            vmax.x = fmaxf(vmax.x, v.x);
            vmax.y = fmaxf(vmax.y, v.y);
            vmax.z = fmaxf(vmax.z, v.z);
            vmax.w = fmaxf(vmax.w, v.w);
        }
        *(float4*)(sm + bin * SM_STRIDE + 4 * c4) = vmax;
    }
    __syncthreads();

    // Coalesced store: this CTA owns channels [half*128, half*128+128) of box
    // n => a contiguous 6272-float span of out[n][c][ph][pw].
    float* obase = out + (size_t)n * (CH * NBINS) + (size_t)half * (128 * NBINS);
#pragma unroll 4
    for (int k = tid; k < 128 * NBINS; k += 256) {
        const int c  = k / NBINS;
        const int bn = k - c * NBINS;
        obase[k] = sm[bn * SM_STRIDE + c];
    }
}

// ---------------------------------------------------------------------------
extern "C" void kernel_launch(void* const* d_in, const int* in_sizes, int n_in,
                              void* d_out, int out_size) {
    const float* feature   = (const float*)d_in[0];
    const float* boxes     = (const float*)d_in[1];
    const int*   batch_idx = (const int*)d_in[2];
    float*       out       = (float*)d_out;

    dim3 tgrid(FHW / 128, CH / 32, BATCH);
    dim3 tblock(32, 8);
    nchw_to_nhwc_kernel<<<tgrid, tblock>>>((const float4*)feature);

    dim3 ggrid(NBOX, 2);
    roi_align_kernel<<<ggrid, 256>>>(boxes, batch_idx, out);
}

// round 3
// speedup vs baseline: 1.3455x; 1.2757x over previous
#include <cuda_runtime.h>
#include <cuda_fp16.h>
#include <math.h>

// Problem constants (fixed shapes from reference setup_inputs)
#define BATCH   2
#define CH      256
#define FH      200
#define FW      304
#define FHW     (FH*FW)          // 60800 (divisible by 128)
#define NBOX    512
#define POOLED  7
#define NBINS   (POOLED*POOLED)  // 49
#define SCALE   0.25f

// Gather staging: 49 bins x (128 ch + 8 pad) floats = 26.7 KB
#define SM_STRIDE 136

// Scratch: fp16 NHWC copy of the feature map (62.3 MB -> L2-resident).
__device__ __half g_nhwc[(size_t)BATCH * FHW * CH];

// ---------------------------------------------------------------------------
// Pass 1: NCHW fp32 -> NHWC fp16 transpose.
// Tile: 64 channels x 128 HW. Block (32,8).
//  - load: 8 x LDG.128 per thread along HW (high MLP)
//  - store: half2 (2 channels) per thread -> 128B coalesced STG rows
// ---------------------------------------------------------------------------
__global__ void nchw_to_nhwc_kernel(const float4* __restrict__ in) {
    __shared__ float tile[128][65];     // [hw][ch]
    const int b   = blockIdx.z;
    const int p04 = blockIdx.x * 32;    // float4 origin along HW (128 floats)
    const int c0  = blockIdx.y * 64;    // channel tile origin
    const int tx  = threadIdx.x, ty = threadIdx.y;

    const float4* src = in + (size_t)b * CH * (FHW / 4);
    __half2*      dst = (__half2*)g_nhwc + (size_t)b * FHW * (CH / 2);

#pragma unroll
    for (int j = 0; j < 8; j++) {
        const int cl = ty + 8 * j;
        const float4 v = src[(size_t)(c0 + cl) * (FHW / 4) + p04 + tx];
        tile[4 * tx + 0][cl] = v.x;
        tile[4 * tx + 1][cl] = v.y;
        tile[4 * tx + 2][cl] = v.z;
        tile[4 * tx + 3][cl] = v.w;
    }
    __syncthreads();

    const int p0 = p04 * 4;
#pragma unroll
    for (int j = 0; j < 16; j++) {
        const int hw = ty + 8 * j;
        dst[(size_t)(p0 + hw) * (CH / 2) + (c0 >> 1) + tx] =
            __floats2half2_rn(tile[hw][2 * tx], tile[hw][2 * tx + 1]);
    }
}

// ---------------------------------------------------------------------------
// Pass 2: RoI Align gather from fp16 NHWC. Two CTAs per box (channel halves).
//   tid & 15  -> uint4 lane: 8 halves = 8 channels (16 lanes x 8 = 128 ch)
//   tid >> 4  -> bin subset (16 subsets, bins stride 16) — whole bins per
//                subset, so the 2x2 sample max needs no reduction.
// Invalid samples have interpolation weights zeroed (== reference's
// where(valid, val, 0) before the max). Interpolation math in fp32.
// Results staged in smem so the final store is fully coalesced.
// ---------------------------------------------------------------------------
__global__ void __launch_bounds__(256, 5)
roi_align_kernel(const float* __restrict__ boxes,
                 const int*   __restrict__ batch_idx,
                 float*       __restrict__ out) {
    __shared__ float sm[NBINS * SM_STRIDE];
    __shared__ int   s_i0[28];          // 0..13: x axis, 14..27: y axis
    __shared__ int   s_i1[28];
    __shared__ float s_lo[28];
    __shared__ float s_hi[28];

    const int n    = blockIdx.x;
    const int half = blockIdx.y;
    const int tid  = threadIdx.x;

    if (tid < 28) {
        const bool isY  = tid >= 14;
        const int  i    = isY ? tid - 14 : tid;
        const float start = boxes[n * 4 + (isY ? 1 : 0)] * SCALE;
        const float end   = boxes[n * 4 + (isY ? 3 : 2)] * SCALE;
        const float sz    = fmaxf(end - start, 1.0f);
        const float bin   = sz / (float)POOLED;
        const int   p     = i >> 1;
        const int   s     = i & 1;
        const float coord = start + ((float)p + ((float)s + 0.5f) * 0.5f) * bin;
        const int   limit = isY ? FH : FW;
        const bool  valid = (coord > -1.0f) && (coord < (float)limit);
        const float cc    = fminf(fmaxf(coord, 0.0f), (float)(limit - 1));
        const int   c0    = (int)floorf(cc);
        const int   c1    = min(c0 + 1, limit - 1);
        float l = cc - (float)c0;
        float h = 1.0f - l;
        if (!valid) { l = 0.0f; h = 0.0f; }
        s_i0[tid] = c0; s_i1[tid] = c1; s_lo[tid] = l; s_hi[tid] = h;
    }
    __syncthreads();

    const int c8 = tid & 15;            // uint4 lane within the 128-ch half
    const int g  = tid >> 4;            // bin subset 0..15
    // Row = 256 ch = 32 uint4; this CTA's half starts at uint4 index half*16.
    const uint4* __restrict__ F =
        (const uint4*)g_nhwc + (size_t)batch_idx[n] * FHW * 32 + half * 16 + c8;

    for (int bin = g; bin < NBINS; bin += 16) {
        const int ph = bin / POOLED;
        const int pw = bin - ph * POOLED;
        float vmax[8];
#pragma unroll
        for (int k = 0; k < 8; k++) vmax[k] = -INFINITY;

#pragma unroll
        for (int s = 0; s < 4; s++) {
            const int sy = s >> 1, sx = s & 1;
            const int iy = 14 + ph * 2 + sy;
            const int ix = pw * 2 + sx;
            const int y0 = s_i0[iy], y1 = s_i1[iy];
            const int x0 = s_i0[ix], x1 = s_i1[ix];
            const float hy = s_hi[iy], ly = s_lo[iy];
            const float hx = s_hi[ix], lx = s_lo[ix];

            const uint4 r00 = F[(size_t)(y0 * FW + x0) * 32];
            const uint4 r01 = F[(size_t)(y0 * FW + x1) * 32];
            const uint4 r10 = F[(size_t)(y1 * FW + x0) * 32];
            const uint4 r11 = F[(size_t)(y1 * FW + x1) * 32];

            const float w00 = hy * hx, w01 = hy * lx;
            const float w10 = ly * hx, w11 = ly * lx;

            const unsigned* p00 = &r00.x;
            const unsigned* p01 = &r01.x;
            const unsigned* p10 = &r10.x;
            const unsigned* p11 = &r11.x;

#pragma unroll
            for (int w = 0; w < 4; w++) {
                const float2 a00 = __half22float2(*(const __half2*)&p00[w]);
                const float2 a01 = __half22float2(*(const __half2*)&p01[w]);
                const float2 a10 = __half22float2(*(const __half2*)&p10[w]);
                const float2 a11 = __half22float2(*(const __half2*)&p11[w]);
                const float vx = w00 * a00.x + w01 * a01.x + w10 * a10.x + w11 * a11.x;
                const float vy = w00 * a00.y + w01 * a01.y + w10 * a10.y + w11 * a11.y;
                vmax[2 * w]     = fmaxf(vmax[2 * w],     vx);
                vmax[2 * w + 1] = fmaxf(vmax[2 * w + 1], vy);
            }
        }
        float* row = sm + bin * SM_STRIDE + 8 * c8;
        *(float4*)(row)     = make_float4(vmax[0], vmax[1], vmax[2], vmax[3]);
        *(float4*)(row + 4) = make_float4(vmax[4], vmax[5], vmax[6], vmax[7]);
    }
    __syncthreads();

    // Coalesced store: this CTA owns a contiguous 6272-float span of out.
    float* obase = out + (size_t)n * (CH * NBINS) + (size_t)half * (128 * NBINS);
#pragma unroll 4
    for (int k = tid; k < 128 * NBINS; k += 256) {
        const int c  = k / NBINS;
        const int bn = k - c * NBINS;
        obase[k] = sm[bn * SM_STRIDE + c];
    }
}

// ---------------------------------------------------------------------------
extern "C" void kernel_launch(void* const* d_in, const int* in_sizes, int n_in,
                              void* d_out, int out_size) {
    const float* feature   = (const float*)d_in[0];
    const float* boxes     = (const float*)d_in[1];
    const int*   batch_idx = (const int*)d_in[2];
    float*       out       = (float*)d_out;

    dim3 tgrid(FHW / 128, CH / 64, BATCH);
    dim3 tblock(32, 8);
    nchw_to_nhwc_kernel<<<tgrid, tblock>>>((const float4*)feature);

    dim3 ggrid(NBOX, 2);
    roi_align_kernel<<<ggrid, 256>>>(boxes, batch_idx, out);
}